// round 5
// baseline (speedup 1.0000x reference)
#include <cuda_runtime.h>
#include <math.h>
#include <stdint.h>

// Problem constants
#define BB 2048
#define TT 500
#define LL 128
#define DD 64
#define UU 128
#define RB 16              // batch rows per block
#define NBLK (BB / RB)     // 128 blocks
#define NTHR 512

typedef unsigned long long u64;

// ---------------------------------------------------------------------------
// Packed f32x2 FMA (FFMA2) — only reachable via PTX fma.rn.f32x2
// ---------------------------------------------------------------------------
__device__ __forceinline__ void fma2(u64 &c, u64 a, u64 b) {
    asm("fma.rn.f32x2 %0, %1, %2, %0;" : "+l"(c) : "l"(a), "l"(b));
}
__device__ __forceinline__ float f2lo(u64 v) { return __uint_as_float((unsigned)v); }
__device__ __forceinline__ float f2hi(u64 v) { return __uint_as_float((unsigned)(v >> 32)); }
__device__ __forceinline__ float f2sum(u64 v) { return f2lo(v) + f2hi(v); }

__device__ __forceinline__ ulonglong2 ld2s(const char *p) {            // LDS.128
    return *reinterpret_cast<const ulonglong2 *>(p);
}
__device__ __forceinline__ ulonglong2 ld2g(const char *p) {            // LDG.128
    return *reinterpret_cast<const ulonglong2 *>(p);
}

// ---------------------------------------------------------------------------
// Streamed weights, pre-packed into [k4][col] float4 layout (prep kernel)
// ---------------------------------------------------------------------------
__device__ float4 g_wihq[16 * 384];   // w_ih[:, 0:64]  : [k4<16][j<384]  (96 KB)
__device__ float4 g_w1q [32 * 128];   // w1             : [k4<32][q<128]  (64 KB)
__device__ float4 g_w2q [32 * 64];    // w2             : [q4<32][d<64]   (32 KB)

__global__ void prep_kernel(const float *__restrict__ w_ih,
                            const float *__restrict__ w1,
                            const float *__restrict__ w2) {
    int idx = blockIdx.x * blockDim.x + threadIdx.x;
    int stride = gridDim.x * blockDim.x;
    for (int i = idx; i < 16 * 384; i += stride) {
        int k4 = i / 384, j = i % 384;
        const float *s = w_ih + j * 65 + 4 * k4;       // row length 65 (last col = dt)
        g_wihq[i] = make_float4(s[0], s[1], s[2], s[3]);
    }
    for (int i = idx; i < 32 * 128; i += stride) {
        int k4 = i / 128, q = i % 128;
        const float *s = w1 + q * 128 + 4 * k4;
        g_w1q[i] = make_float4(s[0], s[1], s[2], s[3]);
    }
    for (int i = idx; i < 32 * 64; i += stride) {
        int q4 = i / 64, d = i % 64;
        const float *s = w2 + d * 128 + 4 * q4;
        g_w2q[i] = make_float4(s[0], s[1], s[2], s[3]);
    }
}

// ---------------------------------------------------------------------------
// Shared memory layout (bytes)
// ---------------------------------------------------------------------------
#define SM_WHH    0
#define SM_WHH_SZ (32 * 384 * 16)            // 196608 : whh4[k4][j] float4
#define SM_H      (SM_WHH + SM_WHH_SZ)
#define SM_H_SZ   (16 * 132 * 4)             // 8448  : h[16][132] (pad 132)
#define SM_U      (SM_H + SM_H_SZ)
#define SM_U_SZ   (16 * 132 * 4)             // 8448
#define SM_P      (SM_U + SM_U_SZ)
#define SM_P_SZ   (16 * 68 * 4)              // 4352  : p[16][68] (pad 68)
#define SM_DT     (SM_P + SM_P_SZ)
#define SM_DT_SZ  (512 * 4)                  // 2048
#define SM_TOTAL  (SM_DT + SM_DT_SZ)         // 219904 <= 232448

__global__ void __launch_bounds__(NTHR, 1)
rnn_kernel(const float *__restrict__ fp,     // first_point [1,B,L]
           const float *__restrict__ ts,     // [T]
           const float *__restrict__ w_hh,   // [384,128]
           const float *__restrict__ w_ih,   // [384,65] (only col 64 read here)
           const float *__restrict__ b_ih,   // [384]
           const float *__restrict__ b_hh,   // [384]
           const float *__restrict__ b1,     // [128]
           const float *__restrict__ b2,     // [64]
           float *__restrict__ out_z,        // [B,T,L]
           float *__restrict__ out_p)        // [B,T,D]
{
    extern __shared__ char sm[];
    float  *h_s  = (float *)(sm + SM_H);
    float  *u_s  = (float *)(sm + SM_U);
    float  *p_s  = (float *)(sm + SM_P);
    float  *dt_s = (float *)(sm + SM_DT);
    float4 *whh4 = (float4 *)(sm + SM_WHH);

    const int tid  = threadIdx.x;
    const int row0 = blockIdx.x * RB;

    // ---- one-time: w_hh -> smem, transposed quad layout whh4[k4*384+j] = w_hh[j][4k4..4k4+3]
    for (int i = tid; i < 32 * 384; i += NTHR) {
        int k4 = i / 384, j = i % 384;
        whh4[i] = *reinterpret_cast<const float4 *>(w_hh + j * 128 + 4 * k4);
    }
    // ---- dt table
    for (int i = tid; i < TT; i += NTHR)
        dt_s[i] = (i == 0) ? 0.0f : (ts[i] - ts[i - 1]);

    // ---- per-thread constants
    // phase A (gates): thread -> hidden column jA, row quartet rqA
    const int jA = tid >> 2, rqA = tid & 3;
    const float bihR = b_ih[jA],        bihZ = b_ih[jA + 128], bihN = b_ih[jA + 256];
    const float bhhR = b_hh[jA],        bhhZ = b_hh[jA + 128], bhhN = b_hh[jA + 256];
    const float wtR  = w_ih[jA * 65 + 64];
    const float wtZ  = w_ih[(jA + 128) * 65 + 64];
    const float wtN  = w_ih[(jA + 256) * 65 + 64];
    // phase D (MLP1): thread -> unit qD, row quartet rqD
    const int qD = tid >> 2, rqD = tid & 3;
    const float b1q = b1[qD];
    // phase E (MLP2): thread -> output dE, rows {rE, rE+8}
    const int dE = tid >> 3, rE = tid & 7;
    const float b2d = b2[dE];
    // coalesced sol_z writer: thread -> (rW, cW..cW+3)
    const int rW = tid >> 5, cW = (tid & 31) * 4;

    // ---- load h0
    {
        float4 v = *reinterpret_cast<const float4 *>(fp + (size_t)(row0 + rW) * LL + cW);
        *reinterpret_cast<float4 *>(&h_s[rW * 132 + cW]) = v;
    }
    __syncthreads();

    for (int t = 0; t < TT; ++t) {
        if (t > 0) {
            // =========== Phase A: GRU gates ===========
            const float dtv = dt_s[t];
            u64 aR[4] = {0, 0, 0, 0}, aZ[4] = {0, 0, 0, 0}, aN[4] = {0, 0, 0, 0};  // gh
            u64 bR[4] = {0, 0, 0, 0}, bZ[4] = {0, 0, 0, 0}, bN[4] = {0, 0, 0, 0};  // gi

            // gh = h @ w_hh^T  (K = 128 -> 32 quads), weights from smem
            {
                const char *wp = (const char *)(whh4 + jA);              // +2048: z, +4096: n
                const char *hp = (const char *)h_s + (size_t)(4 * rqA) * 528;
#pragma unroll 8
                for (int k4 = 0; k4 < 32; ++k4) {
                    ulonglong2 wr = ld2s(wp);
                    ulonglong2 wz = ld2s(wp + 128 * 16);
                    ulonglong2 wn = ld2s(wp + 256 * 16);
#pragma unroll
                    for (int i = 0; i < 4; ++i) {
                        ulonglong2 h = ld2s(hp + i * 528);
                        fma2(aR[i], wr.x, h.x); fma2(aR[i], wr.y, h.y);
                        fma2(aZ[i], wz.x, h.x); fma2(aZ[i], wz.y, h.y);
                        fma2(aN[i], wn.x, h.x); fma2(aN[i], wn.y, h.y);
                    }
                    wp += 384 * 16;
                    hp += 16;
                }
            }
            // gi = p @ w_ih[:, :64]^T  (K = 64 -> 16 quads), weights streamed from L2
            {
                const char *wp = (const char *)(g_wihq + jA);
                const char *pp = (const char *)p_s + (size_t)(4 * rqA) * 272;
#pragma unroll 8
                for (int k4 = 0; k4 < 16; ++k4) {
                    ulonglong2 wr = ld2g(wp);
                    ulonglong2 wz = ld2g(wp + 128 * 16);
                    ulonglong2 wn = ld2g(wp + 256 * 16);
#pragma unroll
                    for (int i = 0; i < 4; ++i) {
                        ulonglong2 p = ld2s(pp + i * 272);
                        fma2(bR[i], wr.x, p.x); fma2(bR[i], wr.y, p.y);
                        fma2(bZ[i], wz.x, p.x); fma2(bZ[i], wz.y, p.y);
                        fma2(bN[i], wn.x, p.x); fma2(bN[i], wn.y, p.y);
                    }
                    wp += 384 * 16;
                    pp += 16;
                }
            }
            // gates + state update
            float hn[4];
#pragma unroll
            for (int i = 0; i < 4; ++i) {
                int rrow = 4 * rqA + i;
                float giR = f2sum(bR[i]) + bihR + dtv * wtR;
                float giZ = f2sum(bZ[i]) + bihZ + dtv * wtZ;
                float giN = f2sum(bN[i]) + bihN + dtv * wtN;
                float ghR = f2sum(aR[i]) + bhhR;
                float ghZ = f2sum(aZ[i]) + bhhZ;
                float ghN = f2sum(aN[i]) + bhhN;
                float rg = 1.0f / (1.0f + expf(-(giR + ghR)));
                float zg = 1.0f / (1.0f + expf(-(giZ + ghZ)));
                float ng = tanhf(giN + rg * ghN);
                hn[i] = (1.0f - zg) * ng + zg * h_s[rrow * 132 + jA];
            }
            __syncthreads();   // all phase-A reads of h_s done
#pragma unroll
            for (int i = 0; i < 4; ++i)
                h_s[(4 * rqA + i) * 132 + jA] = hn[i];
            __syncthreads();   // h_s now holds h_t
        }

        // =========== sol_z[t] writer (coalesced 512B/warp) ===========
        {
            float4 v = *reinterpret_cast<const float4 *>(&h_s[rW * 132 + cW]);
            *reinterpret_cast<float4 *>(
                &out_z[((size_t)(row0 + rW) * TT + t) * LL + cW]) = v;
        }

        // =========== Phase D: u = tanh(h @ w1^T + b1) ===========
        {
            u64 c0 = 0, c1 = 0, c2 = 0, c3 = 0;
            const char *wp = (const char *)(g_w1q + qD);
            const char *hp = (const char *)h_s + (size_t)(4 * rqD) * 528;
#pragma unroll 8
            for (int k4 = 0; k4 < 32; ++k4) {
                ulonglong2 w  = ld2g(wp);
                ulonglong2 h0 = ld2s(hp);
                ulonglong2 h1 = ld2s(hp + 528);
                ulonglong2 h2 = ld2s(hp + 1056);
                ulonglong2 h3 = ld2s(hp + 1584);
                fma2(c0, w.x, h0.x); fma2(c0, w.y, h0.y);
                fma2(c1, w.x, h1.x); fma2(c1, w.y, h1.y);
                fma2(c2, w.x, h2.x); fma2(c2, w.y, h2.y);
                fma2(c3, w.x, h3.x); fma2(c3, w.y, h3.y);
                wp += 128 * 16;
                hp += 16;
            }
            u_s[(4 * rqD + 0) * 132 + qD] = tanhf(f2sum(c0) + b1q);
            u_s[(4 * rqD + 1) * 132 + qD] = tanhf(f2sum(c1) + b1q);
            u_s[(4 * rqD + 2) * 132 + qD] = tanhf(f2sum(c2) + b1q);
            u_s[(4 * rqD + 3) * 132 + qD] = tanhf(f2sum(c3) + b1q);
        }
        __syncthreads();       // u_s ready

        // =========== Phase E: p = u @ w2^T + b2 ===========
        {
            u64 e0 = 0, e1 = 0;
            const char *wp  = (const char *)(g_w2q + dE);
            const char *up0 = (const char *)u_s + (size_t)rE * 528;
            const char *up1 = up0 + 8 * 528;
#pragma unroll 8
            for (int q4 = 0; q4 < 32; ++q4) {
                ulonglong2 w  = ld2g(wp);
                ulonglong2 ua = ld2s(up0);
                ulonglong2 ub = ld2s(up1);
                fma2(e0, w.x, ua.x); fma2(e0, w.y, ua.y);
                fma2(e1, w.x, ub.x); fma2(e1, w.y, ub.y);
                wp += 64 * 16;
                up0 += 16;
                up1 += 16;
            }
            float pa = f2sum(e0) + b2d;
            float pb = f2sum(e1) + b2d;
            p_s[rE * 68 + dE]       = pa;
            p_s[(rE + 8) * 68 + dE] = pb;
            out_p[((size_t)(row0 + rE) * TT + t) * DD + dE]     = pa;
            out_p[((size_t)(row0 + rE + 8) * TT + t) * DD + dE] = pb;
        }
        __syncthreads();       // p_s ready for next step's phase A
    }
}

// ---------------------------------------------------------------------------
// Launch
// ---------------------------------------------------------------------------
extern "C" void kernel_launch(void *const *d_in, const int *in_sizes, int n_in,
                              void *d_out, int out_size) {
    const float *fp   = (const float *)d_in[0];  // first_point [1,B,L]
    const float *ts   = (const float *)d_in[1];  // [T]
    const float *w_ih = (const float *)d_in[2];  // [384,65]
    const float *w_hh = (const float *)d_in[3];  // [384,128]
    const float *b_ih = (const float *)d_in[4];
    const float *b_hh = (const float *)d_in[5];
    const float *w1   = (const float *)d_in[6];  // [128,128]
    const float *b1   = (const float *)d_in[7];
    const float *w2   = (const float *)d_in[8];  // [64,128]
    const float *b2   = (const float *)d_in[9];

    float *out_z = (float *)d_out;                       // sol_z  [1,B,T,L]
    float *out_p = out_z + (size_t)BB * TT * LL;         // pred_x [1,B,T,D]

    prep_kernel<<<64, 256>>>(w_ih, w1, w2);

    cudaFuncSetAttribute(rnn_kernel, cudaFuncAttributeMaxDynamicSharedMemorySize,
                         SM_TOTAL);
    rnn_kernel<<<NBLK, NTHR, SM_TOTAL>>>(fp, ts, w_hh, w_ih, b_ih, b_hh, b1, b2,
                                         out_z, out_p);
}

// round 6
// speedup vs baseline: 1.5950x; 1.5950x over previous
#include <cuda_runtime.h>
#include <math.h>
#include <stdint.h>

// Problem constants
#define BB 2048
#define TT 500
#define LL 128
#define DD 64
#define UU 128
#define RB 16              // batch rows per block
#define NBLK (BB / RB)     // 128 blocks
#define NTHR 512

typedef unsigned long long u64;

// ---------------------------------------------------------------------------
// Packed f32x2 FMA (FFMA2) — only reachable via PTX fma.rn.f32x2
// ---------------------------------------------------------------------------
__device__ __forceinline__ void fma2(u64 &c, u64 a, u64 b) {
    asm("fma.rn.f32x2 %0, %1, %2, %0;" : "+l"(c) : "l"(a), "l"(b));
}
__device__ __forceinline__ float f2sum(u64 v) {
    return __uint_as_float((unsigned)v) + __uint_as_float((unsigned)(v >> 32));
}
__device__ __forceinline__ ulonglong2 ld2s(const char *p) {            // LDS.128
    return *reinterpret_cast<const ulonglong2 *>(p);
}
__device__ __forceinline__ ulonglong2 ld2g(const char *p) {            // LDG.128
    return *reinterpret_cast<const ulonglong2 *>(p);
}

__device__ __forceinline__ float sig_f(float x) {          // fast sigmoid
    return __fdividef(1.0f, 1.0f + __expf(-x));
}
__device__ __forceinline__ float tanh_f(float x) {         // fast tanh
    return 2.0f * __fdividef(1.0f, 1.0f + __expf(-2.0f * x)) - 1.0f;
}

// ---------------------------------------------------------------------------
// Streamed weights, pre-packed into [k4][col] float4 layout (prep kernel)
// ---------------------------------------------------------------------------
__device__ float4 g_wihq[16 * 384];   // w_ih[:, 0:64]  : [k4<16][j<384]
__device__ float4 g_w1q [32 * 128];   // w1             : [k4<32][q<128]
__device__ float4 g_w2q [32 * 64];    // w2             : [q4<32][d<64]

__global__ void prep_kernel(const float *__restrict__ w_ih,
                            const float *__restrict__ w1,
                            const float *__restrict__ w2) {
    int idx = blockIdx.x * blockDim.x + threadIdx.x;
    int stride = gridDim.x * blockDim.x;
    for (int i = idx; i < 16 * 384; i += stride) {
        int k4 = i / 384, j = i % 384;
        const float *s = w_ih + j * 65 + 4 * k4;       // row length 65 (last = dt)
        g_wihq[i] = make_float4(s[0], s[1], s[2], s[3]);
    }
    for (int i = idx; i < 32 * 128; i += stride) {
        int k4 = i / 128, q = i % 128;
        const float *s = w1 + q * 128 + 4 * k4;
        g_w1q[i] = make_float4(s[0], s[1], s[2], s[3]);
    }
    for (int i = idx; i < 32 * 64; i += stride) {
        int q4 = i / 64, d = i % 64;
        const float *s = w2 + d * 128 + 4 * q4;
        g_w2q[i] = make_float4(s[0], s[1], s[2], s[3]);
    }
}

// ---------------------------------------------------------------------------
// Shared memory layout (bytes)
// ---------------------------------------------------------------------------
#define SM_WHH    0
#define SM_WHH_SZ (32 * 384 * 16)            // 196608 : whh4[k4][j] float4
#define SM_H      (SM_WHH + SM_WHH_SZ)
#define SM_H_SZ   (16 * 132 * 4)             // 8448  : h[16][132]
#define SM_U      (SM_H + SM_H_SZ)
#define SM_U_SZ   (16 * 132 * 4)             // 8448
#define SM_P      (SM_U + SM_U_SZ)
#define SM_P_SZ   (16 * 68 * 4)              // 4352  : p[16][68]
#define SM_DT     (SM_P + SM_P_SZ)
#define SM_DT_SZ  (512 * 4)
#define SM_TOTAL  (SM_DT + SM_DT_SZ)         // 219904

__global__ void __launch_bounds__(NTHR, 1)
rnn_kernel(const float *__restrict__ fp,     // first_point [1,B,L]
           const float *__restrict__ ts,     // [T]
           const float *__restrict__ w_hh,   // [384,128]
           const float *__restrict__ w_ih,   // [384,65]
           const float *__restrict__ b_ih,   // [384]
           const float *__restrict__ b_hh,   // [384]
           const float *__restrict__ b1,     // [128]
           const float *__restrict__ b2,     // [64]
           float *__restrict__ out_z,        // [B,T,L]
           float *__restrict__ out_p)        // [B,T,D]
{
    extern __shared__ char sm[];
    float  *h_s  = (float *)(sm + SM_H);
    float  *u_s  = (float *)(sm + SM_U);
    float  *p_s  = (float *)(sm + SM_P);
    float  *dt_s = (float *)(sm + SM_DT);
    float4 *whh4 = (float4 *)(sm + SM_WHH);

    const int tid  = threadIdx.x;
    const int lane = tid & 31;
    const int warp = tid >> 5;
    const int row0 = blockIdx.x * RB;

    // ---- one-time: w_hh -> smem, whh4[k4*384 + j] = w_hh[j][4k4..4k4+3]
    for (int i = tid; i < 32 * 384; i += NTHR) {
        int k4 = i / 384, j = i % 384;
        whh4[i] = *reinterpret_cast<const float4 *>(w_hh + j * 128 + 4 * k4);
    }
    for (int i = tid; i < TT; i += NTHR)
        dt_s[i] = (i == 0) ? 0.0f : (ts[i] - ts[i - 1]);

    // ---- phase A mapping: (jA in 0..127, ksA in 0..1 lane-bit4, r0A row half)
    const int jA  = ((warp & 7) << 4) | (lane & 15);
    const int ksA = lane >> 4;
    const int r0A = (warp >> 3) * 8;
    const float cR  = b_ih[jA] + b_hh[jA];
    const float cZ  = b_ih[jA + 128] + b_hh[jA + 128];
    const float biN = b_ih[jA + 256];
    const float bhN = b_hh[jA + 256];
    const float wtR = w_ih[jA * 65 + 64];
    const float wtZ = w_ih[(jA + 128) * 65 + 64];
    const float wtN = w_ih[(jA + 256) * 65 + 64];

    // ---- phase D mapping: (q4 in 0..31, rqD rows, ksD lane bits 3..4)
    const int q4  = ((warp & 3) << 3) | (lane & 7);
    const int ksD = lane >> 3;                 // 0..3
    const int rqD = warp >> 2;                 // 0..3
    const float4 b1v = *reinterpret_cast<const float4 *>(b1 + 4 * q4);

    // ---- phase E mapping: (d4 in 0..15, rqE rows, ksE lane bits 2..4)
    const int d4  = ((warp & 3) << 2) | (lane & 3);
    const int ksE = lane >> 2;                 // 0..7
    const int rqE = warp >> 2;                 // 0..3
    const float4 b2v = *reinterpret_cast<const float4 *>(b2 + 4 * d4);

    // ---- coalesced sol_z writer mapping
    const int rW = tid >> 5, cW = (tid & 31) * 4;

    // ---- load h0
    {
        float4 v = *reinterpret_cast<const float4 *>(fp + (size_t)(row0 + rW) * LL + cW);
        *reinterpret_cast<float4 *>(&h_s[rW * 132 + cW]) = v;
    }
    __syncthreads();

    for (int t = 0; t < TT; ++t) {
        if (t > 0) {
            // =========== Phase A: GRU gates, tile 8 rows x 3 gates, ksplit 2 =====
            u64 aR[8], aZ[8], aN1[8], aN2[8];   // N1 = i_n (from p), N2 = h_n (from h)
#pragma unroll
            for (int i = 0; i < 8; ++i) { aR[i] = 0; aZ[i] = 0; aN1[i] = 0; aN2[i] = 0; }

            // gh = h @ w_hh^T : K-half interleaved k4 = 2*kk + ksA
            {
                const char *wp = (const char *)(whh4 + ksA * 384 + jA);
                const char *hp = (const char *)h_s + (size_t)(r0A * 132 + 4 * ksA) * 4;
#pragma unroll 4
                for (int kk = 0; kk < 16; ++kk) {
                    ulonglong2 wr = ld2s(wp);
                    ulonglong2 wz = ld2s(wp + 128 * 16);
                    ulonglong2 wn = ld2s(wp + 256 * 16);
#pragma unroll
                    for (int i = 0; i < 8; ++i) {
                        ulonglong2 h = ld2s(hp + i * 528);
                        fma2(aR[i],  wr.x, h.x); fma2(aR[i],  wr.y, h.y);
                        fma2(aZ[i],  wz.x, h.x); fma2(aZ[i],  wz.y, h.y);
                        fma2(aN2[i], wn.x, h.x); fma2(aN2[i], wn.y, h.y);
                    }
                    wp += 2 * 384 * 16;
                    hp += 32;
                }
            }
            // gi = p @ w_ih[:, :64]^T : k4 = 2*kk + ksA (8 iters)
            {
                const char *wp = (const char *)(g_wihq + ksA * 384 + jA);
                const char *pp = (const char *)p_s + (size_t)(r0A * 68 + 4 * ksA) * 4;
#pragma unroll 2
                for (int kk = 0; kk < 8; ++kk) {
                    ulonglong2 wr = ld2g(wp);
                    ulonglong2 wz = ld2g(wp + 128 * 16);
                    ulonglong2 wn = ld2g(wp + 256 * 16);
#pragma unroll
                    for (int i = 0; i < 8; ++i) {
                        ulonglong2 p = ld2s(pp + i * 272);
                        fma2(aR[i],  wr.x, p.x); fma2(aR[i],  wr.y, p.y);
                        fma2(aZ[i],  wz.x, p.x); fma2(aZ[i],  wz.y, p.y);
                        fma2(aN1[i], wn.x, p.x); fma2(aN1[i], wn.y, p.y);
                    }
                    wp += 2 * 384 * 16;
                    pp += 32;
                }
            }
            // reduce ks pairs + gates
            const float dtv = dt_s[t];
            float hn[8];
#pragma unroll
            for (int i = 0; i < 8; ++i) {
                float sR = f2sum(aR[i]);  sR += __shfl_xor_sync(0xffffffffu, sR, 16);
                float sZ = f2sum(aZ[i]);  sZ += __shfl_xor_sync(0xffffffffu, sZ, 16);
                float sI = f2sum(aN1[i]); sI += __shfl_xor_sync(0xffffffffu, sI, 16);
                float sH = f2sum(aN2[i]); sH += __shfl_xor_sync(0xffffffffu, sH, 16);
                float rg = sig_f(sR + cR + dtv * wtR);
                float zg = sig_f(sZ + cZ + dtv * wtZ);
                float ng = tanh_f(sI + biN + dtv * wtN + rg * (sH + bhN));
                float hold = h_s[(r0A + i) * 132 + jA];
                hn[i] = (1.0f - zg) * ng + zg * hold;
            }
            __syncthreads();   // all reads of old h/p done
            if (ksA == 0) {
#pragma unroll
                for (int i = 0; i < 8; ++i)
                    h_s[(r0A + i) * 132 + jA] = hn[i];
            }
            __syncthreads();   // h_s now holds h_t
        }

        // =========== sol_z[t] writer (coalesced 512B/warp) ===========
        {
            float4 v = *reinterpret_cast<const float4 *>(&h_s[rW * 132 + cW]);
            *reinterpret_cast<float4 *>(
                &out_z[((size_t)(row0 + rW) * TT + t) * LL + cW]) = v;
        }

        // =========== Phase D: u = tanh(h @ w1^T + b1), tile 4x4, ksplit 4 =====
        {
            u64 c[16];
#pragma unroll
            for (int i = 0; i < 16; ++i) c[i] = 0;
            const char *wp = (const char *)(g_w1q + ksD * 128 + 4 * q4);
            const char *hp = (const char *)h_s + (size_t)(rqD * 4 * 132 + 4 * ksD) * 4;
#pragma unroll 2
            for (int kk = 0; kk < 8; ++kk) {
                ulonglong2 w0 = ld2g(wp);
                ulonglong2 w1r = ld2g(wp + 16);
                ulonglong2 w2r = ld2g(wp + 32);
                ulonglong2 w3r = ld2g(wp + 48);
#pragma unroll
                for (int i = 0; i < 4; ++i) {
                    ulonglong2 h = ld2s(hp + i * 528);
                    fma2(c[i * 4 + 0], w0.x,  h.x); fma2(c[i * 4 + 0], w0.y,  h.y);
                    fma2(c[i * 4 + 1], w1r.x, h.x); fma2(c[i * 4 + 1], w1r.y, h.y);
                    fma2(c[i * 4 + 2], w2r.x, h.x); fma2(c[i * 4 + 2], w2r.y, h.y);
                    fma2(c[i * 4 + 3], w3r.x, h.x); fma2(c[i * 4 + 3], w3r.y, h.y);
                }
                wp += 4 * 128 * 16;
                hp += 64;
            }
#pragma unroll
            for (int i = 0; i < 4; ++i) {
                float s0 = f2sum(c[i * 4 + 0]);
                float s1 = f2sum(c[i * 4 + 1]);
                float s2 = f2sum(c[i * 4 + 2]);
                float s3 = f2sum(c[i * 4 + 3]);
                s0 += __shfl_xor_sync(0xffffffffu, s0, 8);
                s1 += __shfl_xor_sync(0xffffffffu, s1, 8);
                s2 += __shfl_xor_sync(0xffffffffu, s2, 8);
                s3 += __shfl_xor_sync(0xffffffffu, s3, 8);
                s0 += __shfl_xor_sync(0xffffffffu, s0, 16);
                s1 += __shfl_xor_sync(0xffffffffu, s1, 16);
                s2 += __shfl_xor_sync(0xffffffffu, s2, 16);
                s3 += __shfl_xor_sync(0xffffffffu, s3, 16);
                if (ksD == 0) {
                    float4 uv = make_float4(tanh_f(s0 + b1v.x), tanh_f(s1 + b1v.y),
                                            tanh_f(s2 + b1v.z), tanh_f(s3 + b1v.w));
                    *reinterpret_cast<float4 *>(&u_s[(rqD * 4 + i) * 132 + 4 * q4]) = uv;
                }
            }
        }
        __syncthreads();       // u_s ready

        // =========== Phase E: p = u @ w2^T + b2, tile 4x4, ksplit 8 ===========
        {
            u64 c[16];
#pragma unroll
            for (int i = 0; i < 16; ++i) c[i] = 0;
            const char *wp = (const char *)(g_w2q + ksE * 64 + 4 * d4);
            const char *up = (const char *)u_s + (size_t)(rqE * 4 * 132 + 4 * ksE) * 4;
#pragma unroll
            for (int kk = 0; kk < 4; ++kk) {
                ulonglong2 w0 = ld2g(wp);
                ulonglong2 w1r = ld2g(wp + 16);
                ulonglong2 w2r = ld2g(wp + 32);
                ulonglong2 w3r = ld2g(wp + 48);
#pragma unroll
                for (int i = 0; i < 4; ++i) {
                    ulonglong2 u = ld2s(up + i * 528);
                    fma2(c[i * 4 + 0], w0.x,  u.x); fma2(c[i * 4 + 0], w0.y,  u.y);
                    fma2(c[i * 4 + 1], w1r.x, u.x); fma2(c[i * 4 + 1], w1r.y, u.y);
                    fma2(c[i * 4 + 2], w2r.x, u.x); fma2(c[i * 4 + 2], w2r.y, u.y);
                    fma2(c[i * 4 + 3], w3r.x, u.x); fma2(c[i * 4 + 3], w3r.y, u.y);
                }
                wp += 8 * 64 * 16;
                up += 128;
            }
#pragma unroll
            for (int i = 0; i < 4; ++i) {
                float s0 = f2sum(c[i * 4 + 0]);
                float s1 = f2sum(c[i * 4 + 1]);
                float s2 = f2sum(c[i * 4 + 2]);
                float s3 = f2sum(c[i * 4 + 3]);
                s0 += __shfl_xor_sync(0xffffffffu, s0, 4);
                s1 += __shfl_xor_sync(0xffffffffu, s1, 4);
                s2 += __shfl_xor_sync(0xffffffffu, s2, 4);
                s3 += __shfl_xor_sync(0xffffffffu, s3, 4);
                s0 += __shfl_xor_sync(0xffffffffu, s0, 8);
                s1 += __shfl_xor_sync(0xffffffffu, s1, 8);
                s2 += __shfl_xor_sync(0xffffffffu, s2, 8);
                s3 += __shfl_xor_sync(0xffffffffu, s3, 8);
                s0 += __shfl_xor_sync(0xffffffffu, s0, 16);
                s1 += __shfl_xor_sync(0xffffffffu, s1, 16);
                s2 += __shfl_xor_sync(0xffffffffu, s2, 16);
                s3 += __shfl_xor_sync(0xffffffffu, s3, 16);
                if (ksE == 0) {
                    float4 pv = make_float4(s0 + b2v.x, s1 + b2v.y,
                                            s2 + b2v.z, s3 + b2v.w);
                    int r = rqE * 4 + i;
                    *reinterpret_cast<float4 *>(&p_s[r * 68 + 4 * d4]) = pv;
                    *reinterpret_cast<float4 *>(
                        &out_p[((size_t)(row0 + r) * TT + t) * DD + 4 * d4]) = pv;
                }
            }
        }
        __syncthreads();       // p_s ready for next step's phase A
    }
}

// ---------------------------------------------------------------------------
// Launch
// ---------------------------------------------------------------------------
extern "C" void kernel_launch(void *const *d_in, const int *in_sizes, int n_in,
                              void *d_out, int out_size) {
    const float *fp   = (const float *)d_in[0];
    const float *ts   = (const float *)d_in[1];
    const float *w_ih = (const float *)d_in[2];
    const float *w_hh = (const float *)d_in[3];
    const float *b_ih = (const float *)d_in[4];
    const float *b_hh = (const float *)d_in[5];
    const float *w1   = (const float *)d_in[6];
    const float *b1   = (const float *)d_in[7];
    const float *w2   = (const float *)d_in[8];
    const float *b2   = (const float *)d_in[9];

    float *out_z = (float *)d_out;                       // sol_z  [1,B,T,L]
    float *out_p = out_z + (size_t)BB * TT * LL;         // pred_x [1,B,T,D]

    prep_kernel<<<64, 256>>>(w_ih, w1, w2);

    cudaFuncSetAttribute(rnn_kernel, cudaFuncAttributeMaxDynamicSharedMemorySize,
                         SM_TOTAL);
    rnn_kernel<<<NBLK, NTHR, SM_TOTAL>>>(fp, ts, w_hh, w_ih, b_ih, b_hh, b1, b2,
                                         out_z, out_p);
}